// round 2
// baseline (speedup 1.0000x reference)
#include <cuda_runtime.h>
#include <cstdint>

#define BB 8
#define CC 128
#define NN 4096
#define KK 8
#define TM 128
#define TN 64

// ---- device scratch (no allocations allowed) ----
__device__ float g_xx[BB * NN];
__device__ int   g_idx[BB * NN * KK];
__device__ float g_G[(size_t)BB * CC * NN];
__device__ float g_WT[CC * CC];
__device__ float g_PT[(size_t)BB * NN * CC];   // points transposed: [b][n][c]

__device__ __forceinline__ float lrelu(float x) { return x > 0.f ? x : 0.01f * x; }

extern __shared__ __align__(16) float smem[];

// ---------------- xx[b,n] = sum_c points^2 ----------------
__global__ void xx_kernel(const float* __restrict__ pts) {
    int t = blockIdx.x * blockDim.x + threadIdx.x;   // b*N + n
    int b = t >> 12, n = t & (NN - 1);
    const float* p = pts + (size_t)b * CC * NN + n;
    float s = 0.f;
#pragma unroll
    for (int c = 0; c < CC; c++) { float v = p[(size_t)c * NN]; s = fmaf(v, v, s); }
    g_xx[t] = s;
}

// ---------------- transpose conv2_w -> g_WT[c][o] ----------------
__global__ void wt_kernel(const float* __restrict__ w) {
    int t = blockIdx.x * blockDim.x + threadIdx.x;   // o*128 + c
    int o = t >> 7, c = t & 127;
    g_WT[c * CC + o] = w[t];
}

// ---------------- transpose points -> g_PT[b][n][c] ----------------
__global__ void pt_kernel(const float* __restrict__ pts) {
    __shared__ float t[32][33];
    int b  = blockIdx.z;
    int c0 = blockIdx.y * 32, n0 = blockIdx.x * 32;
    for (int i = threadIdx.y; i < 32; i += 8)
        t[i][threadIdx.x] = pts[(size_t)b * CC * NN + (size_t)(c0 + i) * NN + n0 + threadIdx.x];
    __syncthreads();
    for (int i = threadIdx.y; i < 32; i += 8)
        g_PT[((size_t)b * NN + n0 + i) * CC + c0 + threadIdx.x] = t[threadIdx.x][i];
}

// ---------------- fused Gram + top-8 (the hot kernel) ----------------
// Grid (N/TM, B), 256 threads. Computes neg_sq_dist row tiles and keeps a
// per-row sorted top-8 (jax top_k tie-break: lower index first -> strict >).
// Inner product done in packed dual-FP32 (fma.rn.f32x2 -> FFMA2).
#define FMA2(ACC, A, Bv) asm("fma.rn.f32x2 %0,%1,%2,%0;" : "+l"(ACC) : "l"(A), "l"(Bv))

__global__ void __launch_bounds__(256, 1) gram_topk_kernel(const float* __restrict__ pts) {
    float* As = smem;                  // [CC][TM]  = 16384 f
    float* Bs = As + CC * TM;          // [CC][TN]  =  8192 f
    float* Ss = Bs + CC * TN;          // [TM][65]  =  8320 f (pad 65 -> no bank conflict)
    float* xr = Ss + TM * 65;          // [TM]
    float* xc = xr + TM;               // [TN]

    const int tid  = threadIdx.x;
    const int b    = blockIdx.y;
    const int row0 = blockIdx.x * TM;
    const float* P = pts + (size_t)b * CC * NN;

    // Load A tile once: As[k][r] = P[k*N + row0 + r]   (coalesced)
    for (int i = tid; i < CC * TM / 4; i += 256) {
        int k = i >> 5;                 // TM/4 = 32
        int r4 = (i & 31) << 2;
        *(float4*)(As + k * TM + r4) = *(const float4*)(P + (size_t)k * NN + row0 + r4);
    }
    if (tid < TM) xr[tid] = g_xx[b * NN + row0 + tid];

    // per-row top-8 (owned by tid < 128, row = row0 + tid), kept sorted desc
    float sc[8]; int ix[8];
#pragma unroll
    for (int p = 0; p < 8; p++) { sc[p] = -3e38f; ix[p] = 0; }

    const int r0 = (tid & 15) * 8;      // 8 rows  (4 row-pairs)
    const int c0 = (tid >> 4) * 4;      // 4 cols
    unsigned aBase = (unsigned)__cvta_generic_to_shared(As + r0);
    unsigned bBase = (unsigned)__cvta_generic_to_shared(Bs + c0);

    for (int ct = 0; ct < NN / TN; ct++) {
        const int col0 = ct * TN;

        // load B tile + xc  (safe: prior compute finished before prior scan-sync)
        for (int i = tid; i < CC * TN / 4; i += 256) {
            int k = i >> 4;             // TN/4 = 16
            int c4 = (i & 15) << 2;
            *(float4*)(Bs + k * TN + c4) = *(const float4*)(P + (size_t)k * NN + col0 + c4);
        }
        if (tid < TN) xc[tid] = g_xx[b * NN + col0 + tid];
        __syncthreads();

        unsigned long long acc[16];     // acc[j*4+p] : col j, row-pair p
#pragma unroll
        for (int i = 0; i < 16; i++) acc[i] = 0ULL;

#pragma unroll 4
        for (int k = 0; k < CC; k++) {
            unsigned long long a0, a1, a2, a3, b0, b1, b2, b3;
            float bx, by, bz, bw;
            asm volatile("ld.shared.v2.b64 {%0,%1},[%2];"
                         : "=l"(a0), "=l"(a1) : "r"(aBase + k * (TM * 4)));
            asm volatile("ld.shared.v2.b64 {%0,%1},[%2];"
                         : "=l"(a2), "=l"(a3) : "r"(aBase + k * (TM * 4) + 16));
            asm volatile("ld.shared.v4.b32 {%0,%1,%2,%3},[%4];"
                         : "=f"(bx), "=f"(by), "=f"(bz), "=f"(bw) : "r"(bBase + k * (TN * 4)));
            asm("mov.b64 %0,{%1,%1};" : "=l"(b0) : "f"(bx));
            asm("mov.b64 %0,{%1,%1};" : "=l"(b1) : "f"(by));
            asm("mov.b64 %0,{%1,%1};" : "=l"(b2) : "f"(bz));
            asm("mov.b64 %0,{%1,%1};" : "=l"(b3) : "f"(bw));
            FMA2(acc[0],  a0, b0); FMA2(acc[1],  a1, b0); FMA2(acc[2],  a2, b0); FMA2(acc[3],  a3, b0);
            FMA2(acc[4],  a0, b1); FMA2(acc[5],  a1, b1); FMA2(acc[6],  a2, b1); FMA2(acc[7],  a3, b1);
            FMA2(acc[8],  a0, b2); FMA2(acc[9],  a1, b2); FMA2(acc[10], a2, b2); FMA2(acc[11], a3, b2);
            FMA2(acc[12], a0, b3); FMA2(acc[13], a1, b3); FMA2(acc[14], a2, b3); FMA2(acc[15], a3, b3);
        }

        // scores: neg_sq_dist = 2*inner - xx[row] - xx[col]
        float xcv[4] = { xc[c0], xc[c0 + 1], xc[c0 + 2], xc[c0 + 3] };
#pragma unroll
        for (int p = 0; p < 4; p++) {
            int r = r0 + 2 * p;
            float xrl = xr[r], xrh = xr[r + 1];
#pragma unroll
            for (int j = 0; j < 4; j++) {
                float lo, hi;
                asm("mov.b64 {%0,%1},%2;" : "=f"(lo), "=f"(hi) : "l"(acc[j * 4 + p]));
                Ss[r * 65 + c0 + j]       = 2.f * lo - xrl - xcv[j];
                Ss[(r + 1) * 65 + c0 + j] = 2.f * hi - xrh - xcv[j];
            }
        }
        __syncthreads();

        // owner scan: insert tile's 64 scores into the sorted top-8
        if (tid < TM) {
            const float* rowp = Ss + tid * 65;
#pragma unroll 4
            for (int j = 0; j < TN; j++) {
                float s = rowp[j];
                if (s > sc[7]) {
                    int idv = col0 + j;
#pragma unroll
                    for (int p = 7; p >= 1; --p) {
                        bool up  = s > sc[p - 1];
                        float ns = up ? sc[p - 1] : ((s > sc[p]) ? s   : sc[p]);
                        int   ni = up ? ix[p - 1] : ((s > sc[p]) ? idv : ix[p]);
                        sc[p] = ns; ix[p] = ni;
                    }
                    if (s > sc[0]) { sc[0] = s; ix[0] = idv; }
                }
            }
        }
        __syncthreads();
    }

    if (tid < TM) {
        int n = row0 + tid;
#pragma unroll
        for (int p = 0; p < 8; p++) g_idx[((size_t)b * NN + n) * 8 + p] = ix[p];
    }
}

// ---------------- fp64 exact rescoring of the 8 candidates -> true order ----------------
// The top-8 SET from fp32 is correct (verified by the order-invariant output).
// fp32 ordering can flip adjacent ranks whose true-distance gap is below fp32
// accumulation noise (~1e-4); re-sorting by exact fp64 distance fixes it.
__global__ void refine_kernel() {
    int b    = blockIdx.y;
    int n    = blockIdx.x * 8 + (threadIdx.x >> 5);
    int lane = threadIdx.x & 31;

    const float* ct = g_PT + ((size_t)b * NN + n) * CC;
    float cn[4];
#pragma unroll
    for (int i = 0; i < 4; i++) cn[i] = ct[lane + 32 * i];

    int* ip = g_idx + ((size_t)b * NN + n) * 8;
    double d[8]; int id[8];
#pragma unroll
    for (int k = 0; k < 8; k++) {
        int j = ip[k]; id[k] = j;
        const float* nt = g_PT + ((size_t)b * NN + j) * CC;
        double s = 0.0;
#pragma unroll
        for (int i = 0; i < 4; i++) {
            double df = (double)cn[i] - (double)nt[lane + 32 * i];
            s += df * df;
        }
#pragma unroll
        for (int o = 16; o > 0; o >>= 1) s += __shfl_xor_sync(0xffffffffu, s, o);
        d[k] = s;
    }

    if (lane == 0) {
        // insertion sort ascending by (d, idx): matches jax top_k (desc score,
        // lower index first on ties)
        for (int a = 1; a < 8; a++) {
            double dv = d[a]; int iv = id[a]; int p = a - 1;
            while (p >= 0 && (d[p] > dv || (d[p] == dv && id[p] > iv))) {
                d[p + 1] = d[p]; id[p + 1] = id[p]; p--;
            }
            d[p + 1] = dv; id[p + 1] = iv;
        }
#pragma unroll
        for (int k = 0; k < 8; k++) ip[k] = id[k];
    }
}

// ---------------- G = conv2_w @ lrelu(points)  (per batch 128x4096x128) ----------------
__global__ void __launch_bounds__(256, 1) ggemm_kernel(const float* __restrict__ pts) {
    float* Ws = smem;              // [c][o] 128x128
    float* Fs = Ws + CC * CC;      // [c][n] 128x128
    const int tid = threadIdx.x;
    const int b = blockIdx.y;
    const int n0 = blockIdx.x * 128;
    const float* P = pts + (size_t)b * CC * NN;

    for (int i = tid; i < CC * CC / 4; i += 256)
        *(float4*)(Ws + i * 4) = *(const float4*)(g_WT + i * 4);
    for (int i = tid; i < CC * 128 / 4; i += 256) {
        int c = i >> 5; int n4 = (i & 31) << 2;
        float4 v = *(const float4*)(P + (size_t)c * NN + n0 + n4);
        v.x = lrelu(v.x); v.y = lrelu(v.y); v.z = lrelu(v.z); v.w = lrelu(v.w);
        *(float4*)(Fs + c * 128 + n4) = v;
    }
    __syncthreads();

    const int o0 = (tid & 15) * 8;
    const int m0 = (tid >> 4) * 8;
    float acc[8][8];
#pragma unroll
    for (int i = 0; i < 8; i++)
#pragma unroll
        for (int j = 0; j < 8; j++) acc[i][j] = 0.f;

#pragma unroll 2
    for (int k = 0; k < CC; k++) {
        float4 a0 = *(float4*)(Ws + k * CC + o0);
        float4 a1 = *(float4*)(Ws + k * CC + o0 + 4);
        float4 f0 = *(float4*)(Fs + k * 128 + m0);
        float4 f1 = *(float4*)(Fs + k * 128 + m0 + 4);
        float a[8] = { a0.x, a0.y, a0.z, a0.w, a1.x, a1.y, a1.z, a1.w };
        float f[8] = { f0.x, f0.y, f0.z, f0.w, f1.x, f1.y, f1.z, f1.w };
#pragma unroll
        for (int i = 0; i < 8; i++)
#pragma unroll
            for (int j = 0; j < 8; j++) acc[i][j] = fmaf(a[i], f[j], acc[i][j]);
    }

    float* Gp = g_G + (size_t)b * CC * NN;
#pragma unroll
    for (int i = 0; i < 8; i++) {
        float4 v0 = make_float4(acc[i][0], acc[i][1], acc[i][2], acc[i][3]);
        float4 v1 = make_float4(acc[i][4], acc[i][5], acc[i][6], acc[i][7]);
        *(float4*)(Gp + (size_t)(o0 + i) * NN + n0 + m0)     = v0;
        *(float4*)(Gp + (size_t)(o0 + i) * NN + n0 + m0 + 4) = v1;
    }
}

// ---------------- out[b,c,n] = points + (lrelu(center) + sum_k lrelu(nbr))/9 ----------------
__global__ void out_kernel(const float* __restrict__ pts, float* __restrict__ out) {
    __shared__ float row[NN];
    int b = blockIdx.y, c = blockIdx.x;
    const float* P = pts + ((size_t)b * CC + c) * NN;
    for (int i = threadIdx.x; i < NN / 4; i += 256)
        *(float4*)(row + i * 4) = *(const float4*)(P + i * 4);
    __syncthreads();
    for (int n = threadIdx.x; n < NN; n += 256) {
        const int4* ip = (const int4*)(g_idx + ((size_t)b * NN + n) * 8);
        int4 i0 = ip[0], i1 = ip[1];
        float x = row[n];
        float s = lrelu(x);
        s += lrelu(row[i0.x]); s += lrelu(row[i0.y]); s += lrelu(row[i0.z]); s += lrelu(row[i0.w]);
        s += lrelu(row[i1.x]); s += lrelu(row[i1.y]); s += lrelu(row[i1.z]); s += lrelu(row[i1.w]);
        out[((size_t)b * CC + c) * NN + n] = x + s * (1.f / 9.f);
    }
}

// ---------------- gnn[b,o,n,k] = G[b,o,idx[b,n,k]] ----------------
__global__ void gnn_kernel(float* __restrict__ gnn) {
    __shared__ float row[NN];
    int b = blockIdx.y, o = blockIdx.x;
    const float* Gp = g_G + ((size_t)b * CC + o) * NN;
    for (int i = threadIdx.x; i < NN / 4; i += 256)
        *(float4*)(row + i * 4) = *(const float4*)(Gp + i * 4);
    __syncthreads();
    float* dst = gnn + ((size_t)b * CC + o) * NN * KK;
    const int* ip = g_idx + (size_t)b * NN * KK;
    for (int e = threadIdx.x; e < NN * KK; e += 256)
        dst[e] = row[ip[e]];
}

// ---------------- launch ----------------
extern "C" void kernel_launch(void* const* d_in, const int* in_sizes, int n_in,
                              void* d_out, int out_size) {
    (void)in_sizes; (void)n_in; (void)out_size;
    const float* pts    = (const float*)d_in[0];
    // d_in[1] (W) is provably unused: mean(softmax) == 1/9 exactly.
    const float* conv2w = (const float*)d_in[2];
    float* out = (float*)d_out;
    float* gnn = out + (size_t)BB * CC * NN;

    cudaFuncSetAttribute(gram_topk_kernel, cudaFuncAttributeMaxDynamicSharedMemorySize, 132352);
    cudaFuncSetAttribute(ggemm_kernel,     cudaFuncAttributeMaxDynamicSharedMemorySize, 131072);

    xx_kernel<<<BB * NN / 256, 256>>>(pts);
    wt_kernel<<<CC * CC / 256, 256>>>(conv2w);
    pt_kernel<<<dim3(NN / 32, CC / 32, BB), dim3(32, 8)>>>(pts);
    gram_topk_kernel<<<dim3(NN / TM, BB), 256, 132352>>>(pts);
    refine_kernel<<<dim3(NN / 8, BB), 256>>>();
    ggemm_kernel<<<dim3(NN / 128, BB), 256, 131072>>>(pts);
    out_kernel<<<dim3(CC, BB), 256>>>(pts, out);
    gnn_kernel<<<dim3(CC, BB), 256>>>(gnn);
}

// round 5
// speedup vs baseline: 1.5137x; 1.5137x over previous
#include <cuda_runtime.h>
#include <cstdint>

#define BB 8
#define CC 128
#define NN 4096
#define KK 8
#define TM 128
#define TN 64
#define KCAND 8

// ---- device scratch (no allocations allowed) ----
__device__ float g_xx[BB * NN];
__device__ int   g_idx[BB * NN * KK];
__device__ float g_G[(size_t)BB * CC * NN];
__device__ float g_WT[CC * CC];
__device__ float g_PT[(size_t)BB * NN * CC];   // points transposed: [b][n][c]

__device__ __forceinline__ float lrelu(float x) { return x > 0.f ? x : 0.01f * x; }

extern __shared__ __align__(16) float smem[];

// ---------------- xx[b,n] = sum_c points^2 ----------------
__global__ void xx_kernel(const float* __restrict__ pts) {
    int t = blockIdx.x * blockDim.x + threadIdx.x;   // b*N + n
    int b = t >> 12, n = t & (NN - 1);
    const float* p = pts + (size_t)b * CC * NN + n;
    float s = 0.f;
#pragma unroll
    for (int c = 0; c < CC; c++) { float v = p[(size_t)c * NN]; s = fmaf(v, v, s); }
    g_xx[t] = s;
}

// ---------------- transpose conv2_w -> g_WT[c][o] ----------------
__global__ void wt_kernel(const float* __restrict__ w) {
    int t = blockIdx.x * blockDim.x + threadIdx.x;   // o*128 + c
    int o = t >> 7, c = t & 127;
    g_WT[c * CC + o] = w[t];
}

// ---------------- transpose points -> g_PT[b][n][c] ----------------
__global__ void pt_kernel(const float* __restrict__ pts) {
    __shared__ float t[32][33];
    int b  = blockIdx.z;
    int c0 = blockIdx.y * 32, n0 = blockIdx.x * 32;
    for (int i = threadIdx.y; i < 32; i += 8)
        t[i][threadIdx.x] = pts[(size_t)b * CC * NN + (size_t)(c0 + i) * NN + n0 + threadIdx.x];
    __syncthreads();
    for (int i = threadIdx.y; i < 32; i += 8)
        g_PT[((size_t)b * NN + n0 + i) * CC + c0 + threadIdx.x] = t[threadIdx.x][i];
}

// ---------------- fused Gram + top-8 (the hot kernel) ----------------
// 256 threads; thread = 4 consecutive rows (lane) x 8 cols (warp).
// A: one conflict-free LDS.128 per k. B: two warp-broadcast ld.shared.v2.b64.
// Per-(row,col) accumulation is the same sequential FFMA2 chain over k as the
// round-2 kernel, and scores use the SAME expression 2*inner - xr - xc, so
// the fp32 selection decisions are bit-identical to the kernel that matched
// the reference's top_k at every row. fp64 refine reorders within the set.
#define FMA2(ACC, A, Bv) asm("fma.rn.f32x2 %0,%1,%2,%0;" : "+l"(ACC) : "l"(A), "l"(Bv))

#define SMEM_FLOATS (CC * TM + CC * TN + 16 * 132 + TN + TM)

__global__ void __launch_bounds__(256, 2) gram_topk_kernel(const float* __restrict__ pts) {
    float* As  = smem;                 // [k][r] 128x128 = 64KB
    float* Bs  = As + CC * TM;         // [k][c] 128x64  = 32KB
    float* Ss  = Bs + CC * TN;         // [16][132] col-major chunk
    float* xcs = Ss + 16 * 132;        // [64]
    float* xrs = xcs + TN;             // [128]

    const int tid  = threadIdx.x;
    const int lane = tid & 31;
    const int warp = tid >> 5;
    const int b    = blockIdx.y;
    const int row0 = blockIdx.x * TM;
    const float* P = pts + (size_t)b * CC * NN;

    // Load A tile once (coalesced, k-major, rows contiguous)
    for (int i = tid; i < CC * TM / 4; i += 256) {
        int k = i >> 5, r4 = (i & 31) << 2;
        *(float4*)(As + k * TM + r4) = *(const float4*)(P + (size_t)k * NN + row0 + r4);
    }
    if (tid < TM) xrs[tid] = g_xx[b * NN + row0 + tid];

    // sorted top-8 per owner thread (tid<128 owns row row0+tid)
    float sc[KCAND]; int ix[KCAND];
#pragma unroll
    for (int p = 0; p < KCAND; p++) { sc[p] = -3e38f; ix[p] = 0; }

    unsigned aAddr = (unsigned)__cvta_generic_to_shared(As) + lane * 16;
    unsigned bAddr = (unsigned)__cvta_generic_to_shared(Bs) + warp * 32;

    for (int ct = 0; ct < NN / TN; ct++) {
        const int col0 = ct * TN;

        for (int i = tid; i < CC * TN / 4; i += 256) {
            int k = i >> 4, c4 = (i & 15) << 2;
            *(float4*)(Bs + k * TN + c4) = *(const float4*)(P + (size_t)k * NN + col0 + c4);
        }
        if (tid < TN) xcs[tid] = g_xx[b * NN + col0 + tid];
        __syncthreads();

        unsigned long long acc[16];    // acc[r*4+cp] = (score[r][2cp], score[r][2cp+1])
#pragma unroll
        for (int i = 0; i < 16; i++) acc[i] = 0ULL;

#pragma unroll 4
        for (int k = 0; k < CC; k++) {
            float a0, a1, a2, a3;
            asm volatile("ld.shared.v4.b32 {%0,%1,%2,%3},[%4];"
                         : "=f"(a0), "=f"(a1), "=f"(a2), "=f"(a3)
                         : "r"(aAddr + k * (TM * 4)));
            unsigned long long B0, B1, B2, B3, A0, A1, A2, A3;
            asm volatile("ld.shared.v2.b64 {%0,%1},[%2];"
                         : "=l"(B0), "=l"(B1) : "r"(bAddr + k * (TN * 4)));
            asm volatile("ld.shared.v2.b64 {%0,%1},[%2];"
                         : "=l"(B2), "=l"(B3) : "r"(bAddr + k * (TN * 4) + 16));
            asm("mov.b64 %0,{%1,%1};" : "=l"(A0) : "f"(a0));
            asm("mov.b64 %0,{%1,%1};" : "=l"(A1) : "f"(a1));
            asm("mov.b64 %0,{%1,%1};" : "=l"(A2) : "f"(a2));
            asm("mov.b64 %0,{%1,%1};" : "=l"(A3) : "f"(a3));
            FMA2(acc[0],  A0, B0); FMA2(acc[1],  A0, B1); FMA2(acc[2],  A0, B2); FMA2(acc[3],  A0, B3);
            FMA2(acc[4],  A1, B0); FMA2(acc[5],  A1, B1); FMA2(acc[6],  A1, B2); FMA2(acc[7],  A1, B3);
            FMA2(acc[8],  A2, B0); FMA2(acc[9],  A2, B1); FMA2(acc[10], A2, B2); FMA2(acc[11], A2, B3);
            FMA2(acc[12], A3, B0); FMA2(acc[13], A3, B1); FMA2(acc[14], A3, B2); FMA2(acc[15], A3, B3);
        }

        float xcv[8];
#pragma unroll
        for (int j = 0; j < 8; j++) xcv[j] = xcs[warp * 8 + j];

        // stage + scan in 4 chunks of 16 cols (warps 2q,2q+1 own chunk q)
#pragma unroll
        for (int q = 0; q < 4; q++) {
            if ((warp >> 1) == q) {
                float xrv[4] = { xrs[lane * 4 + 0], xrs[lane * 4 + 1],
                                 xrs[lane * 4 + 2], xrs[lane * 4 + 3] };
#pragma unroll
                for (int cp = 0; cp < 4; cp++) {
                    float lo[4], hi[4];
#pragma unroll
                    for (int r = 0; r < 4; r++)
                        asm("mov.b64 {%0,%1},%2;" : "=f"(lo[r]), "=f"(hi[r]) : "l"(acc[r * 4 + cp]));
                    float xl = xcv[2 * cp], xh = xcv[2 * cp + 1];
                    int cc = (warp & 1) * 8 + 2 * cp;
                    // EXACT round-2 score expression (matches reference noise):
                    float4 vlo = make_float4(2.f * lo[0] - xrv[0] - xl, 2.f * lo[1] - xrv[1] - xl,
                                             2.f * lo[2] - xrv[2] - xl, 2.f * lo[3] - xrv[3] - xl);
                    float4 vhi = make_float4(2.f * hi[0] - xrv[0] - xh, 2.f * hi[1] - xrv[1] - xh,
                                             2.f * hi[2] - xrv[2] - xh, 2.f * hi[3] - xrv[3] - xh);
                    *(float4*)(Ss + cc * 132 + lane * 4)       = vlo;   // conflict-free
                    *(float4*)(Ss + (cc + 1) * 132 + lane * 4) = vhi;
                }
            }
            __syncthreads();
            if (tid < TM) {
#pragma unroll 4
                for (int j = 0; j < 16; j++) {
                    float s = Ss[j * 132 + tid];
                    if (s > sc[KCAND - 1]) {
                        int idv = col0 + q * 16 + j;
#pragma unroll
                        for (int p = KCAND - 1; p >= 1; --p) {
                            bool up  = s > sc[p - 1];
                            float ns = up ? sc[p - 1] : ((s > sc[p]) ? s   : sc[p]);
                            int   ni = up ? ix[p - 1] : ((s > sc[p]) ? idv : ix[p]);
                            sc[p] = ns; ix[p] = ni;
                        }
                        if (s > sc[0]) { sc[0] = s; ix[0] = idv; }
                    }
                }
            }
            __syncthreads();
        }
    }

    if (tid < TM) {
        size_t base = ((size_t)b * NN + row0 + tid) * KK;
#pragma unroll
        for (int p = 0; p < KK; p++) g_idx[base + p] = ix[p];
    }
}

// ---------------- fp64 exact rescoring of the 8 selected -> true order ----------------
// The SET from the fp32 selection matches the reference (same score arithmetic
// as the verified round-2 kernel); fp64 reorder within the set fixes the rare
// adjacent-rank flips from fp32 accumulation noise.
__global__ void refine_kernel() {
    int b    = blockIdx.y;
    int n    = blockIdx.x * 8 + (threadIdx.x >> 5);
    int lane = threadIdx.x & 31;

    const float* ct = g_PT + ((size_t)b * NN + n) * CC;
    float cn[4];
#pragma unroll
    for (int i = 0; i < 4; i++) cn[i] = ct[lane + 32 * i];

    int* ip = g_idx + ((size_t)b * NN + n) * KK;
    double d[KK]; int id[KK];
#pragma unroll
    for (int k = 0; k < KK; k++) {
        int j = ip[k]; id[k] = j;
        const float* nt = g_PT + ((size_t)b * NN + j) * CC;
        double s = 0.0;
#pragma unroll
        for (int i = 0; i < 4; i++) {
            double df = (double)cn[i] - (double)nt[lane + 32 * i];
            s += df * df;
        }
#pragma unroll
        for (int o = 16; o > 0; o >>= 1) s += __shfl_xor_sync(0xffffffffu, s, o);
        d[k] = s;
    }

    if (lane == 0) {
        // insertion sort ascending by (d, idx): matches jax top_k ordering
        for (int a = 1; a < KK; a++) {
            double dv = d[a]; int iv = id[a]; int p = a - 1;
            while (p >= 0 && (d[p] > dv || (d[p] == dv && id[p] > iv))) {
                d[p + 1] = d[p]; id[p + 1] = id[p]; p--;
            }
            d[p + 1] = dv; id[p + 1] = iv;
        }
#pragma unroll
        for (int k = 0; k < KK; k++) ip[k] = id[k];
    }
}

// ---------------- G = conv2_w @ lrelu(points)  (per batch 128x4096x128) ----------------
__global__ void __launch_bounds__(256, 1) ggemm_kernel(const float* __restrict__ pts) {
    float* Ws = smem;              // [c][o] 128x128
    float* Fs = Ws + CC * CC;      // [c][n] 128x128
    const int tid = threadIdx.x;
    const int b = blockIdx.y;
    const int n0 = blockIdx.x * 128;
    const float* P = pts + (size_t)b * CC * NN;

    for (int i = tid; i < CC * CC / 4; i += 256)
        *(float4*)(Ws + i * 4) = *(const float4*)(g_WT + i * 4);
    for (int i = tid; i < CC * 128 / 4; i += 256) {
        int c = i >> 5; int n4 = (i & 31) << 2;
        float4 v = *(const float4*)(P + (size_t)c * NN + n0 + n4);
        v.x = lrelu(v.x); v.y = lrelu(v.y); v.z = lrelu(v.z); v.w = lrelu(v.w);
        *(float4*)(Fs + c * 128 + n4) = v;
    }
    __syncthreads();

    const int o0 = (tid & 15) * 8;
    const int m0 = (tid >> 4) * 8;
    float acc[8][8];
#pragma unroll
    for (int i = 0; i < 8; i++)
#pragma unroll
        for (int j = 0; j < 8; j++) acc[i][j] = 0.f;

#pragma unroll 2
    for (int k = 0; k < CC; k++) {
        float4 a0 = *(float4*)(Ws + k * CC + o0);
        float4 a1 = *(float4*)(Ws + k * CC + o0 + 4);
        float4 f0 = *(float4*)(Fs + k * 128 + m0);
        float4 f1 = *(float4*)(Fs + k * 128 + m0 + 4);
        float a[8] = { a0.x, a0.y, a0.z, a0.w, a1.x, a1.y, a1.z, a1.w };
        float f[8] = { f0.x, f0.y, f0.z, f0.w, f1.x, f1.y, f1.z, f1.w };
#pragma unroll
        for (int i = 0; i < 8; i++)
#pragma unroll
            for (int j = 0; j < 8; j++) acc[i][j] = fmaf(a[i], f[j], acc[i][j]);
    }

    float* Gp = g_G + (size_t)b * CC * NN;
#pragma unroll
    for (int i = 0; i < 8; i++) {
        float4 v0 = make_float4(acc[i][0], acc[i][1], acc[i][2], acc[i][3]);
        float4 v1 = make_float4(acc[i][4], acc[i][5], acc[i][6], acc[i][7]);
        *(float4*)(Gp + (size_t)(o0 + i) * NN + n0 + m0)     = v0;
        *(float4*)(Gp + (size_t)(o0 + i) * NN + n0 + m0 + 4) = v1;
    }
}

// ---------------- out[b,c,n] = points + (lrelu(center) + sum_k lrelu(nbr))/9 ----------------
__global__ void out_kernel(const float* __restrict__ pts, float* __restrict__ out) {
    __shared__ float row[NN];
    int b = blockIdx.y, c = blockIdx.x;
    const float* P = pts + ((size_t)b * CC + c) * NN;
    for (int i = threadIdx.x; i < NN / 4; i += 256)
        *(float4*)(row + i * 4) = *(const float4*)(P + i * 4);
    __syncthreads();
    for (int n = threadIdx.x; n < NN; n += 256) {
        const int4* ip = (const int4*)(g_idx + ((size_t)b * NN + n) * 8);
        int4 i0 = ip[0], i1 = ip[1];
        float x = row[n];
        float s = lrelu(x);
        s += lrelu(row[i0.x]); s += lrelu(row[i0.y]); s += lrelu(row[i0.z]); s += lrelu(row[i0.w]);
        s += lrelu(row[i1.x]); s += lrelu(row[i1.y]); s += lrelu(row[i1.z]); s += lrelu(row[i1.w]);
        out[((size_t)b * CC + c) * NN + n] = x + s * (1.f / 9.f);
    }
}

// ---------------- gnn[b,o,n,k] = G[b,o,idx[b,n,k]] ----------------
__global__ void gnn_kernel(float* __restrict__ gnn) {
    __shared__ float row[NN];
    int b = blockIdx.y, o = blockIdx.x;
    const float* Gp = g_G + ((size_t)b * CC + o) * NN;
    for (int i = threadIdx.x; i < NN / 4; i += 256)
        *(float4*)(row + i * 4) = *(const float4*)(Gp + i * 4);
    __syncthreads();
    float* dst = gnn + ((size_t)b * CC + o) * NN * KK;
    const int* ip = g_idx + (size_t)b * NN * KK;
    for (int e = threadIdx.x; e < NN * KK; e += 256)
        dst[e] = row[ip[e]];
}

// ---------------- launch ----------------
extern "C" void kernel_launch(void* const* d_in, const int* in_sizes, int n_in,
                              void* d_out, int out_size) {
    (void)in_sizes; (void)n_in; (void)out_size;
    const float* pts    = (const float*)d_in[0];
    // d_in[1] (W) is provably unused: mean(softmax) == 1/9 exactly.
    const float* conv2w = (const float*)d_in[2];
    float* out = (float*)d_out;
    float* gnn = out + (size_t)BB * CC * NN;

    cudaFuncSetAttribute(gram_topk_kernel, cudaFuncAttributeMaxDynamicSharedMemorySize, SMEM_FLOATS * 4);
    cudaFuncSetAttribute(ggemm_kernel,     cudaFuncAttributeMaxDynamicSharedMemorySize, 131072);

    xx_kernel<<<BB * NN / 256, 256>>>(pts);
    wt_kernel<<<CC * CC / 256, 256>>>(conv2w);
    pt_kernel<<<dim3(NN / 32, CC / 32, BB), dim3(32, 8)>>>(pts);
    gram_topk_kernel<<<dim3(NN / TM, BB), 256, SMEM_FLOATS * 4>>>(pts);
    refine_kernel<<<dim3(NN / 8, BB), 256>>>();
    ggemm_kernel<<<dim3(NN / 128, BB), 256, 131072>>>(pts);
    out_kernel<<<dim3(CC, BB), 256>>>(pts, out);
    gnn_kernel<<<dim3(CC, BB), 256>>>(gnn);
}

// round 6
// speedup vs baseline: 1.6343x; 1.0796x over previous
#include <cuda_runtime.h>
#include <cstdint>

#define BB 8
#define CC 128
#define NN 4096
#define KK 8
#define TM 128
#define TN 64

// ---- device scratch (no allocations allowed) ----
__device__ float g_xx[BB * NN];
__device__ int   g_idx[BB * NN * KK];
__device__ float g_G[(size_t)BB * CC * NN];
__device__ float g_WT[CC * CC];
__device__ float g_PT[(size_t)BB * NN * CC];   // points transposed: [b][n][c]

__device__ __forceinline__ float lrelu(float x) { return x > 0.f ? x : 0.01f * x; }

extern __shared__ __align__(16) float smem[];

// ---------------- xx[b,n] = sum_c points^2 ----------------
__global__ void xx_kernel(const float* __restrict__ pts) {
    int t = blockIdx.x * blockDim.x + threadIdx.x;   // b*N + n
    int b = t >> 12, n = t & (NN - 1);
    const float* p = pts + (size_t)b * CC * NN + n;
    float s = 0.f;
#pragma unroll
    for (int c = 0; c < CC; c++) { float v = p[(size_t)c * NN]; s = fmaf(v, v, s); }
    g_xx[t] = s;
}

// ---------------- transpose conv2_w -> g_WT[c][o] ----------------
__global__ void wt_kernel(const float* __restrict__ w) {
    int t = blockIdx.x * blockDim.x + threadIdx.x;   // o*128 + c
    int o = t >> 7, c = t & 127;
    g_WT[c * CC + o] = w[t];
}

// ---------------- transpose points -> g_PT[b][n][c] ----------------
__global__ void pt_kernel(const float* __restrict__ pts) {
    __shared__ float t[32][33];
    int b  = blockIdx.z;
    int c0 = blockIdx.y * 32, n0 = blockIdx.x * 32;
    for (int i = threadIdx.y; i < 32; i += 8)
        t[i][threadIdx.x] = pts[(size_t)b * CC * NN + (size_t)(c0 + i) * NN + n0 + threadIdx.x];
    __syncthreads();
    for (int i = threadIdx.y; i < 32; i += 8)
        g_PT[((size_t)b * NN + n0 + i) * CC + c0 + threadIdx.x] = t[threadIdx.x][i];
}

// ---------------- fused Gram + top-8 (the hot kernel) ----------------
// 256 threads; thread = 4 consecutive rows (lane) x cols {4w..4w+3, 32+4w..+3}.
// Per-(row,col) FFMA2 accumulation chain over k and the score expression
// 2*inner - xr - xc are bit-identical to the verified round-5 kernel, so the
// fp32 selection decisions match the reference's top_k at every row.
// New structure: each 32-col chunk is staged by ALL 8 warps (4 cols each) and
// scanned by ALL 256 threads (half-row partial top-8s, merged at the end by
// (score desc, idx asc) — set-equivalent to a single ascending scan).
#define FMA2(ACC, A, Bv) asm("fma.rn.f32x2 %0,%1,%2,%0;" : "+l"(ACC) : "l"(A), "l"(Bv))

#define SMEM_FLOATS (CC * TM + CC * TN + 32 * 128)   // 28672 floats = 112KB

__global__ void __launch_bounds__(256, 2) gram_topk_kernel(const float* __restrict__ pts) {
    float* As = smem;                 // [k][r] 128x128 = 64KB
    float* Bs = As + CC * TM;         // [k][c] 128x64  = 32KB
    float* Ss = Bs + CC * TN;         // [32][128] col-major chunk = 16KB (also merge scratch)

    const int tid  = threadIdx.x;
    const int lane = tid & 31;
    const int warp = tid >> 5;
    const int b    = blockIdx.y;
    const int row0 = blockIdx.x * TM;
    const float* P = pts + (size_t)b * CC * NN;

    // Load A tile once (coalesced, k-major, rows contiguous)
    for (int i = tid; i < CC * TM / 4; i += 256) {
        int k = i >> 5, r4 = (i & 31) << 2;
        *(float4*)(As + k * TM + r4) = *(const float4*)(P + (size_t)k * NN + row0 + r4);
    }

    // row norms for this thread's 4 staging rows (same g_xx values as before)
    float4 xrv = *(const float4*)(g_xx + b * NN + row0 + lane * 4);

    // per-thread sorted top-8 partial (thread t: row = t&127, col-half = t>>7)
    float sc[KK]; int ix[KK];
#pragma unroll
    for (int p = 0; p < KK; p++) { sc[p] = -3e38f; ix[p] = 0; }

    unsigned aAddr = (unsigned)__cvta_generic_to_shared(As) + lane * 16;
    unsigned bAddr = (unsigned)__cvta_generic_to_shared(Bs) + warp * 16;

    const int srow  = tid & 127;      // scanned row
    const int shalf = tid >> 7;       // scanned col half (0/1) within chunk

    for (int ct = 0; ct < NN / TN; ct++) {
        const int col0 = ct * TN;

        for (int i = tid; i < CC * TN / 4; i += 256) {
            int k = i >> 4, c4 = (i & 15) << 2;
            *(float4*)(Bs + k * TN + c4) = *(const float4*)(P + (size_t)k * NN + col0 + c4);
        }
        __syncthreads();

        // prefetch this thread's col norms (consumed at staging, hidden by compute)
        float4 xq0 = *(const float4*)(g_xx + b * NN + col0 + 4 * warp);
        float4 xq1 = *(const float4*)(g_xx + b * NN + col0 + 32 + 4 * warp);

        unsigned long long acc[16];   // acc[r*4+cp]: cp 0,1 -> cols 4w+2cp(+1); cp 2,3 -> cols 32+4w+2(cp-2)(+1)
#pragma unroll
        for (int i = 0; i < 16; i++) acc[i] = 0ULL;

#pragma unroll 4
        for (int k = 0; k < CC; k++) {
            float a0, a1, a2, a3;
            asm volatile("ld.shared.v4.b32 {%0,%1,%2,%3},[%4];"
                         : "=f"(a0), "=f"(a1), "=f"(a2), "=f"(a3)
                         : "r"(aAddr + k * (TM * 4)));
            unsigned long long B0, B1, B2, B3, A0, A1, A2, A3;
            asm volatile("ld.shared.v2.b64 {%0,%1},[%2];"
                         : "=l"(B0), "=l"(B1) : "r"(bAddr + k * (TN * 4)));
            asm volatile("ld.shared.v2.b64 {%0,%1},[%2];"
                         : "=l"(B2), "=l"(B3) : "r"(bAddr + k * (TN * 4) + 128));
            asm("mov.b64 %0,{%1,%1};" : "=l"(A0) : "f"(a0));
            asm("mov.b64 %0,{%1,%1};" : "=l"(A1) : "f"(a1));
            asm("mov.b64 %0,{%1,%1};" : "=l"(A2) : "f"(a2));
            asm("mov.b64 %0,{%1,%1};" : "=l"(A3) : "f"(a3));
            FMA2(acc[0],  A0, B0); FMA2(acc[1],  A0, B1); FMA2(acc[2],  A0, B2); FMA2(acc[3],  A0, B3);
            FMA2(acc[4],  A1, B0); FMA2(acc[5],  A1, B1); FMA2(acc[6],  A1, B2); FMA2(acc[7],  A1, B3);
            FMA2(acc[8],  A2, B0); FMA2(acc[9],  A2, B1); FMA2(acc[10], A2, B2); FMA2(acc[11], A2, B3);
            FMA2(acc[12], A3, B0); FMA2(acc[13], A3, B1); FMA2(acc[14], A3, B2); FMA2(acc[15], A3, B3);
        }

        // two 32-col chunks: q=0 -> cols [col0, col0+32) (cp 0,1),
        //                    q=1 -> cols [col0+32, col0+64) (cp 2,3)
#pragma unroll
        for (int q = 0; q < 2; q++) {
            // stage: every warp writes its 4 cols of this chunk (col-major [col][row])
#pragma unroll
            for (int cpp = 0; cpp < 2; cpp++) {
                int cp = q * 2 + cpp;
                float lo[4], hi[4];
#pragma unroll
                for (int r = 0; r < 4; r++)
                    asm("mov.b64 {%0,%1},%2;" : "=f"(lo[r]), "=f"(hi[r]) : "l"(acc[r * 4 + cp]));
                float xl, xh;
                if (q == 0) { xl = (cpp == 0) ? xq0.x : xq0.z; xh = (cpp == 0) ? xq0.y : xq0.w; }
                else        { xl = (cpp == 0) ? xq1.x : xq1.z; xh = (cpp == 0) ? xq1.y : xq1.w; }
                int cl = 4 * warp + 2 * cpp;
                // EXACT score expression (matches reference noise):
                float4 vlo = make_float4(2.f * lo[0] - xrv.x - xl, 2.f * lo[1] - xrv.y - xl,
                                         2.f * lo[2] - xrv.z - xl, 2.f * lo[3] - xrv.w - xl);
                float4 vhi = make_float4(2.f * hi[0] - xrv.x - xh, 2.f * hi[1] - xrv.y - xh,
                                         2.f * hi[2] - xrv.z - xh, 2.f * hi[3] - xrv.w - xh);
                *(float4*)(Ss + cl * 128 + lane * 4)       = vlo;   // conflict-free
                *(float4*)(Ss + (cl + 1) * 128 + lane * 4) = vhi;
            }
            __syncthreads();

            // scan: all 256 threads, thread scans 16 cols (its half) of its row,
            // ascending column order (preserves lower-index-on-tie semantics)
            {
                const int cbase = col0 + q * 32 + shalf * 16;
#pragma unroll 4
                for (int j = 0; j < 16; j++) {
                    float s = Ss[(shalf * 16 + j) * 128 + srow];
                    if (s > sc[KK - 1]) {
                        int idv = cbase + j;
#pragma unroll
                        for (int p = KK - 1; p >= 1; --p) {
                            bool up  = s > sc[p - 1];
                            float ns = up ? sc[p - 1] : ((s > sc[p]) ? s   : sc[p]);
                            int   ni = up ? ix[p - 1] : ((s > sc[p]) ? idv : ix[p]);
                            sc[p] = ns; ix[p] = ni;
                        }
                        if (s > sc[0]) { sc[0] = s; ix[0] = idv; }
                    }
                }
            }
            __syncthreads();
        }
    }

    // merge the two half-row partials by (score desc, idx asc) -> global top-8
    {
        float* msc = Ss;                       // [16][128]
        int*   mix = (int*)(Ss + 16 * 128);    // [16][128]
#pragma unroll
        for (int p = 0; p < KK; p++) {
            msc[(shalf * 8 + p) * 128 + srow] = sc[p];
            mix[(shalf * 8 + p) * 128 + srow] = ix[p];
        }
        __syncthreads();
        if (tid < TM) {
            int sel[KK]; int i = 0, j = 0;
#pragma unroll
            for (int s = 0; s < KK; s++) {
                float av = msc[i * 128 + tid], bv = msc[(8 + j) * 128 + tid];
                int   ai = mix[i * 128 + tid], bi = mix[(8 + j) * 128 + tid];
                bool takeA = (av > bv) || (av == bv && ai < bi);
                sel[s] = takeA ? ai : bi;
                if (takeA) i++; else j++;
            }
            size_t base = ((size_t)b * NN + row0 + tid) * KK;
#pragma unroll
            for (int p = 0; p < KK; p++) g_idx[base + p] = sel[p];
        }
    }
}

// ---------------- fp64 exact rescoring of the 8 selected -> true order ----------------
__global__ void refine_kernel() {
    int b    = blockIdx.y;
    int n    = blockIdx.x * 8 + (threadIdx.x >> 5);
    int lane = threadIdx.x & 31;

    const float* ct = g_PT + ((size_t)b * NN + n) * CC;
    float cn[4];
#pragma unroll
    for (int i = 0; i < 4; i++) cn[i] = ct[lane + 32 * i];

    int* ip = g_idx + ((size_t)b * NN + n) * KK;
    double d[KK]; int id[KK];
#pragma unroll
    for (int k = 0; k < KK; k++) {
        int j = ip[k]; id[k] = j;
        const float* nt = g_PT + ((size_t)b * NN + j) * CC;
        double s = 0.0;
#pragma unroll
        for (int i = 0; i < 4; i++) {
            double df = (double)cn[i] - (double)nt[lane + 32 * i];
            s += df * df;
        }
#pragma unroll
        for (int o = 16; o > 0; o >>= 1) s += __shfl_xor_sync(0xffffffffu, s, o);
        d[k] = s;
    }

    if (lane == 0) {
        // insertion sort ascending by (d, idx): matches jax top_k ordering
        for (int a = 1; a < KK; a++) {
            double dv = d[a]; int iv = id[a]; int p = a - 1;
            while (p >= 0 && (d[p] > dv || (d[p] == dv && id[p] > iv))) {
                d[p + 1] = d[p]; id[p + 1] = id[p]; p--;
            }
            d[p + 1] = dv; id[p + 1] = iv;
        }
#pragma unroll
        for (int k = 0; k < KK; k++) ip[k] = id[k];
    }
}

// ---------------- G = conv2_w @ lrelu(points)  (per batch 128x4096x128) ----------------
__global__ void __launch_bounds__(256, 1) ggemm_kernel(const float* __restrict__ pts) {
    float* Ws = smem;              // [c][o] 128x128
    float* Fs = Ws + CC * CC;      // [c][n] 128x128
    const int tid = threadIdx.x;
    const int b = blockIdx.y;
    const int n0 = blockIdx.x * 128;
    const float* P = pts + (size_t)b * CC * NN;

    for (int i = tid; i < CC * CC / 4; i += 256)
        *(float4*)(Ws + i * 4) = *(const float4*)(g_WT + i * 4);
    for (int i = tid; i < CC * 128 / 4; i += 256) {
        int c = i >> 5; int n4 = (i & 31) << 2;
        float4 v = *(const float4*)(P + (size_t)c * NN + n0 + n4);
        v.x = lrelu(v.x); v.y = lrelu(v.y); v.z = lrelu(v.z); v.w = lrelu(v.w);
        *(float4*)(Fs + c * 128 + n4) = v;
    }
    __syncthreads();

    const int o0 = (tid & 15) * 8;
    const int m0 = (tid >> 4) * 8;
    float acc[8][8];
#pragma unroll
    for (int i = 0; i < 8; i++)
#pragma unroll
        for (int j = 0; j < 8; j++) acc[i][j] = 0.f;

#pragma unroll 2
    for (int k = 0; k < CC; k++) {
        float4 a0 = *(float4*)(Ws + k * CC + o0);
        float4 a1 = *(float4*)(Ws + k * CC + o0 + 4);
        float4 f0 = *(float4*)(Fs + k * 128 + m0);
        float4 f1 = *(float4*)(Fs + k * 128 + m0 + 4);
        float a[8] = { a0.x, a0.y, a0.z, a0.w, a1.x, a1.y, a1.z, a1.w };
        float f[8] = { f0.x, f0.y, f0.z, f0.w, f1.x, f1.y, f1.z, f1.w };
#pragma unroll
        for (int i = 0; i < 8; i++)
#pragma unroll
            for (int j = 0; j < 8; j++) acc[i][j] = fmaf(a[i], f[j], acc[i][j]);
    }

    float* Gp = g_G + (size_t)b * CC * NN;
#pragma unroll
    for (int i = 0; i < 8; i++) {
        float4 v0 = make_float4(acc[i][0], acc[i][1], acc[i][2], acc[i][3]);
        float4 v1 = make_float4(acc[i][4], acc[i][5], acc[i][6], acc[i][7]);
        *(float4*)(Gp + (size_t)(o0 + i) * NN + n0 + m0)     = v0;
        *(float4*)(Gp + (size_t)(o0 + i) * NN + n0 + m0 + 4) = v1;
    }
}

// ---------------- out[b,c,n] = points + (lrelu(center) + sum_k lrelu(nbr))/9 ----------------
__global__ void out_kernel(const float* __restrict__ pts, float* __restrict__ out) {
    __shared__ float row[NN];
    int b = blockIdx.y, c = blockIdx.x;
    const float* P = pts + ((size_t)b * CC + c) * NN;
    for (int i = threadIdx.x; i < NN / 4; i += 256)
        *(float4*)(row + i * 4) = *(const float4*)(P + i * 4);
    __syncthreads();
    for (int n = threadIdx.x; n < NN; n += 256) {
        const int4* ip = (const int4*)(g_idx + ((size_t)b * NN + n) * 8);
        int4 i0 = ip[0], i1 = ip[1];
        float x = row[n];
        float s = lrelu(x);
        s += lrelu(row[i0.x]); s += lrelu(row[i0.y]); s += lrelu(row[i0.z]); s += lrelu(row[i0.w]);
        s += lrelu(row[i1.x]); s += lrelu(row[i1.y]); s += lrelu(row[i1.z]); s += lrelu(row[i1.w]);
        out[((size_t)b * CC + c) * NN + n] = x + s * (1.f / 9.f);
    }
}

// ---------------- gnn[b,o,n,k] = G[b,o,idx[b,n,k]] ----------------
__global__ void gnn_kernel(float* __restrict__ gnn) {
    __shared__ float row[NN];
    int b = blockIdx.y, o = blockIdx.x;
    const float* Gp = g_G + ((size_t)b * CC + o) * NN;
    for (int i = threadIdx.x; i < NN / 4; i += 256)
        *(float4*)(row + i * 4) = *(const float4*)(Gp + i * 4);
    __syncthreads();
    float* dst = gnn + ((size_t)b * CC + o) * NN * KK;
    const int* ip = g_idx + (size_t)b * NN * KK;
    for (int e = threadIdx.x; e < NN * KK; e += 256)
        dst[e] = row[ip[e]];
}

// ---------------- launch ----------------
extern "C" void kernel_launch(void* const* d_in, const int* in_sizes, int n_in,
                              void* d_out, int out_size) {
    (void)in_sizes; (void)n_in; (void)out_size;
    const float* pts    = (const float*)d_in[0];
    // d_in[1] (W) is provably unused: mean(softmax) == 1/9 exactly.
    const float* conv2w = (const float*)d_in[2];
    float* out = (float*)d_out;
    float* gnn = out + (size_t)BB * CC * NN;

    cudaFuncSetAttribute(gram_topk_kernel, cudaFuncAttributeMaxDynamicSharedMemorySize, SMEM_FLOATS * 4);
    cudaFuncSetAttribute(ggemm_kernel,     cudaFuncAttributeMaxDynamicSharedMemorySize, 131072);

    xx_kernel<<<BB * NN / 256, 256>>>(pts);
    wt_kernel<<<CC * CC / 256, 256>>>(conv2w);
    pt_kernel<<<dim3(NN / 32, CC / 32, BB), dim3(32, 8)>>>(pts);
    gram_topk_kernel<<<dim3(NN / TM, BB), 256, SMEM_FLOATS * 4>>>(pts);
    refine_kernel<<<dim3(NN / 8, BB), 256>>>();
    ggemm_kernel<<<dim3(NN / 128, BB), 256, 131072>>>(pts);
    out_kernel<<<dim3(CC, BB), 256>>>(pts, out);
    gnn_kernel<<<dim3(CC, BB), 256>>>(gnn);
}